// round 15
// baseline (speedup 1.0000x reference)
#include <cuda_runtime.h>
#include <cuda_bf16.h>
#include <cstdint>

// Fused conv3x3(pad bottom/right)+bias*scale+maxpool2x2+clamp via raw
// mma.sync.m16n8k16 (bf16 split precision, 3 passes), fragments built entirely
// in registers: no smem, no STS/LDS/LDSM. Warp = m16 tile = 16 conv px = 4
// pooled px. m = 2p + dx + 8*dy -> pool = in-reg max + 1 shfl.
// (Resubmission of R14 — prior round was an infra failure, kernel never ran.)

#define ICN 3
#define IH  512
#define IW  512
#define CH  (IH * IW)
#define OCN 16
#define PHN 256
#define PWN 256

struct CP {
    uint32_t bf[2][2][2][2][32];  // [f][ch][split][reg][lane] bf16x2 B-frags
    int   toff[4][8];             // [tig][slot] float offset (ic*CH+kh*IW+kw)
    int   tkh [4][8];             // kh (999 if k>=27 -> always invalid)
    int   tkw [4][8];
    float bias2[16];              // bias*scale
};
__device__   CP g_cp;
__constant__ CP c_cp;

__device__ __forceinline__ uint32_t bf2pack(float hi, float lo) {  // lo in low half
    uint32_t r;
    asm("cvt.rn.bf16x2.f32 %0, %1, %2;" : "=r"(r) : "f"(hi), "f"(lo));
    return r;
}

__global__ void prep_kernel(const float* __restrict__ w,
                            const float* __restrict__ bias,
                            const float* __restrict__ scale) {
    const int i = threadIdx.x;           // 512 threads
    {   // B fragments: lane-resident layout
        const int lane = i & 31, j = i >> 5;
        const int reg = j & 1, sp = (j >> 1) & 1, ch = (j >> 2) & 1, f = (j >> 3) & 1;
        const int gid = lane >> 2, tig = lane & 3;
        const int n = 8 * f + gid;
        const int k0 = 16 * ch + 8 * reg + 2 * tig;
        const float s = scale[n];
        const float w0 = (k0     < 27) ? w[n * 27 + k0]     * s : 0.0f;
        const float w1 = (k0 + 1 < 27) ? w[n * 27 + k0 + 1] * s : 0.0f;
        uint32_t val;
        if (sp == 0) {
            val = bf2pack(w1, w0);
        } else {
            const uint32_t h = bf2pack(w1, w0);
            const float l0 = w0 - __uint_as_float(h << 16);
            const float l1 = w1 - __uint_as_float(h & 0xFFFF0000u);
            val = bf2pack(l1, l0);
        }
        g_cp.bf[f][ch][sp][reg][lane] = val;
    }
    if (i < 32) {   // tap tables
        const int tig = i & 3, s = i >> 2;
        const int kadd[8] = {0, 1, 8, 9, 16, 17, 24, 25};
        const int k = 2 * tig + kadd[s];
        if (k < 27) {
            const int ic = k / 9, r = k % 9, kh = r / 3, kw = r % 3;
            g_cp.toff[tig][s] = ic * CH + kh * IW + kw;
            g_cp.tkh [tig][s] = kh;
            g_cp.tkw [tig][s] = kw;
        } else {
            g_cp.toff[tig][s] = 0;
            g_cp.tkh [tig][s] = 999;    // forces row-invalid -> 0
            g_cp.tkw [tig][s] = 0;
        }
    }
    if (i < OCN) g_cp.bias2[i] = bias[i] * scale[i];
}

__device__ __forceinline__ void mma16816(float* d, const uint32_t* a, const uint32_t* b) {
    asm volatile(
        "mma.sync.aligned.m16n8k16.row.col.f32.bf16.bf16.f32 "
        "{%0,%1,%2,%3}, {%4,%5,%6,%7}, {%8,%9}, {%0,%1,%2,%3};"
        : "+f"(d[0]), "+f"(d[1]), "+f"(d[2]), "+f"(d[3])
        : "r"(a[0]), "r"(a[1]), "r"(a[2]), "r"(a[3]), "r"(b[0]), "r"(b[1]));
}

__global__ __launch_bounds__(128)
void conv_mma_kernel(const float* __restrict__ x, float* __restrict__ out) {
    const int lane = threadIdx.x & 31;
    const int gid = lane >> 2, tig = lane & 3;

    const int ph  = blockIdx.y;
    const int bi  = blockIdx.z;
    const int pwb = blockIdx.x * 16 + (threadIdx.x >> 5) * 4;   // 4 pooled px / warp

    // Lane's two conv px: rows m=gid (dy=0) and m=gid+8 (dy=1); same p, dx.
    const int p  = gid >> 1;
    const int dx = gid & 1;
    const int ow = 2 * (pwb + p) + dx;
    const int oh0 = 2 * ph;                 // dy=0; dy=1 row = oh0+1

    const float* base = x + (size_t)bi * (ICN * CH) + (size_t)oh0 * IW + ow;

    // ---- load 8 taps x 2 rows (predicated; pad = 0) ----
    float v0[8], v1[8];
#pragma unroll
    for (int s = 0; s < 8; s++) {
        const int off = c_cp.toff[tig][s];
        const int kh  = c_cp.tkh [tig][s];
        const int kw  = c_cp.tkw [tig][s];
        const bool cok = (ow + kw) < IW;
        const bool r0  = cok && (oh0 + kh)     < IH;
        const bool r1  = cok && (oh0 + 1 + kh) < IH;
        v0[s] = r0 ? base[off]      : 0.0f;
        v1[s] = r1 ? base[off + IW] : 0.0f;
    }

    // ---- A fragments: hi/lo split, per k-chunk ----
    // mma frag order: a0=(row gid, k01), a1=(row gid+8, k01),
    //                 a2=(row gid, k89), a3=(row gid+8, k89)
    uint32_t ahi[2][4], alo[2][4];
#pragma unroll
    for (int ch = 0; ch < 2; ch++) {
        const int sb = 4 * ch;
#pragma unroll
        for (int rpair = 0; rpair < 2; rpair++) {
            const int sA = sb + 2 * rpair, sB = sA + 1;
            // dy=0 row (m = gid)
            uint32_t h0 = bf2pack(v0[sB], v0[sA]);
            float l0a = v0[sA] - __uint_as_float(h0 << 16);
            float l0b = v0[sB] - __uint_as_float(h0 & 0xFFFF0000u);
            ahi[ch][2 * rpair + 0] = h0;
            alo[ch][2 * rpair + 0] = bf2pack(l0b, l0a);
            // dy=1 row (m = gid+8)
            uint32_t h1 = bf2pack(v1[sB], v1[sA]);
            float l1a = v1[sA] - __uint_as_float(h1 << 16);
            float l1b = v1[sB] - __uint_as_float(h1 & 0xFFFF0000u);
            ahi[ch][2 * rpair + 1] = h1;
            alo[ch][2 * rpair + 1] = bf2pack(l1b, l1a);
        }
    }

    // ---- B fragments from constant ----
    uint32_t b[2][2][2][2];   // [f][ch][split][reg]
#pragma unroll
    for (int f = 0; f < 2; f++)
#pragma unroll
        for (int ch = 0; ch < 2; ch++)
#pragma unroll
            for (int sp = 0; sp < 2; sp++) {
                b[f][ch][sp][0] = c_cp.bf[f][ch][sp][0][lane];
                b[f][ch][sp][1] = c_cp.bf[f][ch][sp][1][lane];
            }

    // ---- 12 MMAs: per f: (Ahi*Bhi + Alo*Bhi + Ahi*Blo) over 2 chunks ----
    float d[2][4];
#pragma unroll
    for (int f = 0; f < 2; f++) {
        d[f][0] = d[f][1] = d[f][2] = d[f][3] = 0.0f;
#pragma unroll
        for (int ch = 0; ch < 2; ch++) {
            mma16816(d[f], ahi[ch], b[f][ch][0]);
            mma16816(d[f], alo[ch], b[f][ch][0]);
            mma16816(d[f], ahi[ch], b[f][ch][1]);
        }
    }

    // ---- pool (in-reg rows + shfl over dx) + bias' + clamp + store ----
    // d: c0=(gid, n0), c1=(gid, n0+1), c2=(gid+8, n0), c3=(gid+8, n0+1).
    // rows gid / gid+8 = dy 0/1 of the same pooled px; lane^4 = dx partner.
#pragma unroll
    for (int f = 0; f < 2; f++) {
        float c0 = fmaxf(d[f][0], d[f][2]);
        float c1 = fmaxf(d[f][1], d[f][3]);
        c0 = fmaxf(c0, __shfl_xor_sync(0xFFFFFFFFu, c0, 4));
        c1 = fmaxf(c1, __shfl_xor_sync(0xFFFFFFFFu, c1, 4));
        if (dx == f) {   // dx0 lanes store f0, dx1 lanes store f1
            const int n0 = 8 * f + 2 * tig;
            const float y0 = fminf(fmaxf(c0 + c_cp.bias2[n0],     0.0f), 1.0f);
            const float y1 = fminf(fmaxf(c1 + c_cp.bias2[n0 + 1], 0.0f), 1.0f);
            float* o0 = out + (((size_t)(bi * OCN + n0)) * PHN + ph) * PWN + pwb + p;
            o0[0] = y0;
            o0[(size_t)PHN * PWN] = y1;
        }
    }
}

extern "C" void kernel_launch(void* const* d_in, const int* in_sizes, int n_in,
                              void* d_out, int out_size) {
    const float* x     = (const float*)d_in[0];
    const float* w     = (const float*)d_in[1];
    const float* bias  = (const float*)d_in[2];
    const float* scale = (const float*)d_in[3];
    float* out = (float*)d_out;

    const int B = in_sizes[0] / (ICN * IH * IW);   // 32

    prep_kernel<<<1, 512>>>(w, bias, scale);

    void* stage = nullptr;
    cudaGetSymbolAddress(&stage, g_cp);
    cudaMemcpyToSymbolAsync(c_cp, stage, sizeof(CP), 0, cudaMemcpyDeviceToDevice, 0);

    dim3 block(128);                                // 4 warps = 16 pooled px
    dim3 grid(PWN / 16, PHN, B);                    // 16 x 256 x 32
    conv_mma_kernel<<<grid, block>>>(x, out);
}

// round 16
// speedup vs baseline: 10.8880x; 10.8880x over previous
#include <cuda_runtime.h>
#include <cuda_bf16.h>
#include <cstdint>

// Fused conv3x3(pad bottom/right)+bias*scale+maxpool2x2+clamp via raw
// mma.sync.m16n8k16 (bf16 split precision, 3 passes), fragments in registers.
// R15 fix: per-lane tables read via coalesced LDG from global (R15's 2.6ms was
// lane-DIVERGENT __constant__ LDC -> ~600 serialized replays/warp).
// Warp = m16 tile = 16 conv px = 4 pooled px. m = 2p+dx+8dy -> pool = max+shfl.

#define ICN 3
#define IH  512
#define IW  512
#define CH  (IH * IW)
#define OCN 16
#define PHN 256
#define PWN 256

struct CP {
    uint32_t bf[2][2][2][2][32];  // [f][ch][split][reg][lane] bf16x2 B-frags
    int   toff[8][4];             // [slot][tig] float offset (ic*CH+kh*IW+kw)
    int   tkhw[8][4];             // [slot][tig] kh*16+kw (kh=15 -> invalid)
    float bias2[16];              // bias*scale
};
__device__ CP g_cp;

__device__ __forceinline__ uint32_t bf2pack(float hi, float lo) {  // lo in low half
    uint32_t r;
    asm("cvt.rn.bf16x2.f32 %0, %1, %2;" : "=r"(r) : "f"(hi), "f"(lo));
    return r;
}

__global__ void prep_kernel(const float* __restrict__ w,
                            const float* __restrict__ bias,
                            const float* __restrict__ scale) {
    const int i = threadIdx.x;           // 512 threads
    {   // B fragments: lane-resident layout (lane-consecutive -> coalesced LDG)
        const int lane = i & 31, j = i >> 5;
        const int reg = j & 1, sp = (j >> 1) & 1, ch = (j >> 2) & 1, f = (j >> 3) & 1;
        const int gid = lane >> 2, tig = lane & 3;
        const int n = 8 * f + gid;
        const int k0 = 16 * ch + 8 * reg + 2 * tig;
        const float s = scale[n];
        const float w0 = (k0     < 27) ? w[n * 27 + k0]     * s : 0.0f;
        const float w1 = (k0 + 1 < 27) ? w[n * 27 + k0 + 1] * s : 0.0f;
        uint32_t val;
        if (sp == 0) {
            val = bf2pack(w1, w0);
        } else {
            const uint32_t h = bf2pack(w1, w0);
            const float l0 = w0 - __uint_as_float(h << 16);
            const float l1 = w1 - __uint_as_float(h & 0xFFFF0000u);
            val = bf2pack(l1, l0);
        }
        g_cp.bf[f][ch][sp][reg][lane] = val;
    }
    if (i < 32) {   // tap tables
        const int tig = i & 3, s = i >> 2;
        const int kadd[8] = {0, 1, 8, 9, 16, 17, 24, 25};
        const int k = 2 * tig + kadd[s];
        if (k < 27) {
            const int ic = k / 9, r = k % 9, kh = r / 3, kw = r % 3;
            g_cp.toff[s][tig] = ic * CH + kh * IW + kw;
            g_cp.tkhw[s][tig] = kh * 16 + kw;
        } else {
            g_cp.toff[s][tig] = 0;
            g_cp.tkhw[s][tig] = 15 * 16;    // kh=15 -> row check always fails
        }
    }
    if (i < OCN) g_cp.bias2[i] = bias[i] * scale[i];
}

__device__ __forceinline__ void mma16816(float* d, const uint32_t* a, const uint32_t* b) {
    asm volatile(
        "mma.sync.aligned.m16n8k16.row.col.f32.bf16.bf16.f32 "
        "{%0,%1,%2,%3}, {%4,%5,%6,%7}, {%8,%9}, {%0,%1,%2,%3};"
        : "+f"(d[0]), "+f"(d[1]), "+f"(d[2]), "+f"(d[3])
        : "r"(a[0]), "r"(a[1]), "r"(a[2]), "r"(a[3]), "r"(b[0]), "r"(b[1]));
}

__global__ __launch_bounds__(128)
void conv_mma_kernel(const float* __restrict__ x, float* __restrict__ out) {
    const int lane = threadIdx.x & 31;
    const int gid = lane >> 2, tig = lane & 3;

    const int ph  = blockIdx.y;
    const int bi  = blockIdx.z;
    const int pwb = blockIdx.x * 16 + (threadIdx.x >> 5) * 4;   // 4 pooled px / warp

    // Lane's two conv px: rows m=gid (dy=0) and m=gid+8 (dy=1); same p, dx.
    const int p  = gid >> 1;
    const int dx = gid & 1;
    const int ow = 2 * (pwb + p) + dx;
    const int oh0 = 2 * ph;

    const float* base = x + (size_t)bi * (ICN * CH) + (size_t)oh0 * IW + ow;

    // ---- tap tables via broadcast LDG (8 lanes share each address) ----
    int toff[8], tkhw[8];
#pragma unroll
    for (int s = 0; s < 8; s++) {
        toff[s] = __ldg(&g_cp.toff[s][tig]);
        tkhw[s] = __ldg(&g_cp.tkhw[s][tig]);
    }

    // ---- load 8 taps x 2 rows (predicated; pad = 0) ----
    float v0[8], v1[8];
#pragma unroll
    for (int s = 0; s < 8; s++) {
        const int kh = tkhw[s] >> 4, kw = tkhw[s] & 15;
        const bool cok = (ow + kw) < IW;
        const bool r0  = cok && (oh0 + kh)     < IH;
        const bool r1  = cok && (oh0 + 1 + kh) < IH;
        v0[s] = r0 ? base[toff[s]]      : 0.0f;
        v1[s] = r1 ? base[toff[s] + IW] : 0.0f;
    }

    // ---- A fragments: hi/lo split, per k-chunk ----
    // frag order: a0=(row gid,k01), a1=(gid+8,k01), a2=(gid,k89), a3=(gid+8,k89)
    uint32_t ahi[2][4], alo[2][4];
#pragma unroll
    for (int ch = 0; ch < 2; ch++) {
        const int sb = 4 * ch;
#pragma unroll
        for (int rpair = 0; rpair < 2; rpair++) {
            const int sA = sb + 2 * rpair, sB = sA + 1;
            uint32_t h0 = bf2pack(v0[sB], v0[sA]);
            float l0a = v0[sA] - __uint_as_float(h0 << 16);
            float l0b = v0[sB] - __uint_as_float(h0 & 0xFFFF0000u);
            ahi[ch][2 * rpair + 0] = h0;
            alo[ch][2 * rpair + 0] = bf2pack(l0b, l0a);
            uint32_t h1 = bf2pack(v1[sB], v1[sA]);
            float l1a = v1[sA] - __uint_as_float(h1 << 16);
            float l1b = v1[sB] - __uint_as_float(h1 & 0xFFFF0000u);
            ahi[ch][2 * rpair + 1] = h1;
            alo[ch][2 * rpair + 1] = bf2pack(l1b, l1a);
        }
    }

    // ---- B fragments: lane-coalesced LDG (128B per read pair, L2-resident) ----
    uint32_t b[2][2][2][2];   // [f][ch][split][reg]
#pragma unroll
    for (int f = 0; f < 2; f++)
#pragma unroll
        for (int ch = 0; ch < 2; ch++)
#pragma unroll
            for (int sp = 0; sp < 2; sp++) {
                b[f][ch][sp][0] = __ldg(&g_cp.bf[f][ch][sp][0][lane]);
                b[f][ch][sp][1] = __ldg(&g_cp.bf[f][ch][sp][1][lane]);
            }

    // ---- 12 MMAs: per f: (Ahi*Bhi + Alo*Bhi + Ahi*Blo) over 2 chunks ----
    float d[2][4];
#pragma unroll
    for (int f = 0; f < 2; f++) {
        d[f][0] = d[f][1] = d[f][2] = d[f][3] = 0.0f;
#pragma unroll
        for (int ch = 0; ch < 2; ch++) {
            mma16816(d[f], ahi[ch], b[f][ch][0]);
            mma16816(d[f], alo[ch], b[f][ch][0]);
            mma16816(d[f], ahi[ch], b[f][ch][1]);
        }
    }

    // ---- pool (in-reg rows + shfl over dx) + bias' + clamp + store ----
    // d: c0=(gid,n0), c1=(gid,n0+1), c2=(gid+8,n0), c3=(gid+8,n0+1);
    // rows gid/gid+8 = dy 0/1 of one pooled px; lane^4 = dx partner.
#pragma unroll
    for (int f = 0; f < 2; f++) {
        float c0 = fmaxf(d[f][0], d[f][2]);
        float c1 = fmaxf(d[f][1], d[f][3]);
        c0 = fmaxf(c0, __shfl_xor_sync(0xFFFFFFFFu, c0, 4));
        c1 = fmaxf(c1, __shfl_xor_sync(0xFFFFFFFFu, c1, 4));
        if (dx == f) {
            const int n0 = 8 * f + 2 * tig;
            const float y0 = fminf(fmaxf(c0 + __ldg(&g_cp.bias2[n0]),     0.0f), 1.0f);
            const float y1 = fminf(fmaxf(c1 + __ldg(&g_cp.bias2[n0 + 1]), 0.0f), 1.0f);
            float* o0 = out + (((size_t)(bi * OCN + n0)) * PHN + ph) * PWN + pwb + p;
            o0[0] = y0;
            o0[(size_t)PHN * PWN] = y1;
        }
    }
}

extern "C" void kernel_launch(void* const* d_in, const int* in_sizes, int n_in,
                              void* d_out, int out_size) {
    const float* x     = (const float*)d_in[0];
    const float* w     = (const float*)d_in[1];
    const float* bias  = (const float*)d_in[2];
    const float* scale = (const float*)d_in[3];
    float* out = (float*)d_out;

    const int B = in_sizes[0] / (ICN * IH * IW);   // 32

    prep_kernel<<<1, 512>>>(w, bias, scale);

    dim3 block(128);                                // 4 warps = 16 pooled px
    dim3 grid(PWN / 16, PHN, B);                    // 16 x 256 x 32
    conv_mma_kernel<<<grid, block>>>(x, out);
}

// round 17
// speedup vs baseline: 13.1847x; 1.2109x over previous
#include <cuda_runtime.h>
#include <cuda_bf16.h>
#include <cstdint>

// Fused conv3x3(pad bottom/right)+bias*scale+maxpool2x2+clamp via raw
// mma.sync.m16n8k16 (bf16 split, 3 passes), fragments in registers.
// R17: interior fast path (no bounds alu / tkhw loads for 98.5% of warps;
// pad-slot garbage is annihilated by zero B rows k>=27) + 2 vertical m-tiles
// per warp sharing toff tables and B-fragments (per-tile L1 ops 58 -> ~36).

#define ICN 3
#define IH  512
#define IW  512
#define CH  (IH * IW)
#define OCN 16
#define PHN 256
#define PWN 256

struct CP {
    uint32_t bf[2][2][2][2][32];  // [f][ch][split][reg][lane] bf16x2 B-frags
    int   toff[8][4];             // [slot][tig] float offset (ic*CH+kh*IW+kw)
    int   tkhw[8][4];             // [slot][tig] kh*16+kw (kh=15 -> invalid)
    float bias2[16];              // bias*scale
};
__device__ CP g_cp;

__device__ __forceinline__ uint32_t bf2pack(float hi, float lo) {  // lo in low half
    uint32_t r;
    asm("cvt.rn.bf16x2.f32 %0, %1, %2;" : "=r"(r) : "f"(hi), "f"(lo));
    return r;
}

__global__ void prep_kernel(const float* __restrict__ w,
                            const float* __restrict__ bias,
                            const float* __restrict__ scale) {
    const int i = threadIdx.x;           // 512 threads
    {   // B fragments, lane-consecutive (coalesced LDG). Rows k>=27 are ZERO.
        const int lane = i & 31, j = i >> 5;
        const int reg = j & 1, sp = (j >> 1) & 1, ch = (j >> 2) & 1, f = (j >> 3) & 1;
        const int gid = lane >> 2, tig = lane & 3;
        const int n = 8 * f + gid;
        const int k0 = 16 * ch + 8 * reg + 2 * tig;
        const float s = scale[n];
        const float w0 = (k0     < 27) ? w[n * 27 + k0]     * s : 0.0f;
        const float w1 = (k0 + 1 < 27) ? w[n * 27 + k0 + 1] * s : 0.0f;
        uint32_t val;
        if (sp == 0) {
            val = bf2pack(w1, w0);
        } else {
            const uint32_t h = bf2pack(w1, w0);
            const float l0 = w0 - __uint_as_float(h << 16);
            const float l1 = w1 - __uint_as_float(h & 0xFFFF0000u);
            val = bf2pack(l1, l0);
        }
        g_cp.bf[f][ch][sp][reg][lane] = val;
    }
    if (i < 32) {   // tap tables
        const int tig = i & 3, s = i >> 2;
        const int kadd[8] = {0, 1, 8, 9, 16, 17, 24, 25};
        const int k = 2 * tig + kadd[s];
        if (k < 27) {
            const int ic = k / 9, r = k % 9, kh = r / 3, kw = r % 3;
            g_cp.toff[s][tig] = ic * CH + kh * IW + kw;
            g_cp.tkhw[s][tig] = kh * 16 + kw;
        } else {
            g_cp.toff[s][tig] = 0;
            g_cp.tkhw[s][tig] = 15 * 16;    // kh=15 -> edge path zeroes it
        }
    }
    if (i < OCN) g_cp.bias2[i] = bias[i] * scale[i];
}

__device__ __forceinline__ void mma16816(float* d, const uint32_t* a, const uint32_t* b) {
    asm volatile(
        "mma.sync.aligned.m16n8k16.row.col.f32.bf16.bf16.f32 "
        "{%0,%1,%2,%3}, {%4,%5,%6,%7}, {%8,%9}, {%0,%1,%2,%3};"
        : "+f"(d[0]), "+f"(d[1]), "+f"(d[2]), "+f"(d[3])
        : "r"(a[0]), "r"(a[1]), "r"(a[2]), "r"(a[3]), "r"(b[0]), "r"(b[1]));
}

__global__ __launch_bounds__(128)
void conv_mma_kernel(const float* __restrict__ x, float* __restrict__ out) {
    const int lane = threadIdx.x & 31;
    const int gid = lane >> 2, tig = lane & 3;
    const int warp = threadIdx.x >> 5;

    const int phb = blockIdx.y;                   // pooled-row PAIR
    const int bi  = blockIdx.z;
    const int pwb = blockIdx.x * 16 + warp * 4;   // 4 pooled cols / warp

    const int p  = gid >> 1;
    const int dx = gid & 1;
    const int ow = 2 * (pwb + p) + dx;
    const int oh0 = 4 * phb;                      // conv rows oh0..oh0+3 (+kh)

    const float* base = x + (size_t)bi * (ICN * CH) + (size_t)oh0 * IW + ow;

    // ---- tap offsets (broadcast LDG, shared by both tiles) ----
    int toff[8];
#pragma unroll
    for (int s = 0; s < 8; s++) toff[s] = __ldg(&g_cp.toff[s][tig]);

    // ---- B fragments (lane-coalesced LDG, shared by both tiles) ----
    uint32_t b[2][2][2][2];   // [f][ch][split][reg]
#pragma unroll
    for (int f = 0; f < 2; f++)
#pragma unroll
        for (int ch = 0; ch < 2; ch++)
#pragma unroll
            for (int sp = 0; sp < 2; sp++) {
                b[f][ch][sp][0] = __ldg(&g_cp.bf[f][ch][sp][0][lane]);
                b[f][ch][sp][1] = __ldg(&g_cp.bf[f][ch][sp][1][lane]);
            }

    // Interior: every tap of both tiles in-bounds (rows to oh0+5, cols to ow+2).
    const bool interior = (phb != 127) && !((blockIdx.x == 15) && (warp == 3));

#pragma unroll
    for (int t = 0; t < 2; t++) {                 // two vertical m-tiles
        // ---- taps: rows oh0+2t (dy=0), oh0+2t+1 (dy=1) ----
        float v0[8], v1[8];
        if (interior) {
#pragma unroll
            for (int s = 0; s < 8; s++) {
                v0[s] = __ldg(base + toff[s] + (2 * t)     * IW);
                v1[s] = __ldg(base + toff[s] + (2 * t + 1) * IW);
            }
        } else {
#pragma unroll
            for (int s = 0; s < 8; s++) {
                const int khw = __ldg(&g_cp.tkhw[s][tig]);
                const int kh = khw >> 4, kw = khw & 15;
                const bool cok = (ow + kw) < IW;
                const bool r0  = cok && (oh0 + 2 * t + kh)     < IH;
                const bool r1  = cok && (oh0 + 2 * t + 1 + kh) < IH;
                v0[s] = r0 ? __ldg(base + toff[s] + (2 * t)     * IW) : 0.0f;
                v1[s] = r1 ? __ldg(base + toff[s] + (2 * t + 1) * IW) : 0.0f;
            }
        }

        // ---- A fragments: hi/lo split ----
        // a0=(row gid,k01), a1=(gid+8,k01), a2=(gid,k89), a3=(gid+8,k89)
        uint32_t ahi[2][4], alo[2][4];
#pragma unroll
        for (int ch = 0; ch < 2; ch++) {
            const int sb = 4 * ch;
#pragma unroll
            for (int rpair = 0; rpair < 2; rpair++) {
                const int sA = sb + 2 * rpair, sB = sA + 1;
                uint32_t h0 = bf2pack(v0[sB], v0[sA]);
                float l0a = v0[sA] - __uint_as_float(h0 << 16);
                float l0b = v0[sB] - __uint_as_float(h0 & 0xFFFF0000u);
                ahi[ch][2 * rpair + 0] = h0;
                alo[ch][2 * rpair + 0] = bf2pack(l0b, l0a);
                uint32_t h1 = bf2pack(v1[sB], v1[sA]);
                float l1a = v1[sA] - __uint_as_float(h1 << 16);
                float l1b = v1[sB] - __uint_as_float(h1 & 0xFFFF0000u);
                ahi[ch][2 * rpair + 1] = h1;
                alo[ch][2 * rpair + 1] = bf2pack(l1b, l1a);
            }
        }

        // ---- 12 MMAs: per f: Ahi*Bhi + Alo*Bhi + Ahi*Blo over 2 chunks ----
        float d[2][4];
#pragma unroll
        for (int f = 0; f < 2; f++) {
            d[f][0] = d[f][1] = d[f][2] = d[f][3] = 0.0f;
#pragma unroll
            for (int ch = 0; ch < 2; ch++) {
                mma16816(d[f], ahi[ch], b[f][ch][0]);
                mma16816(d[f], alo[ch], b[f][ch][0]);
                mma16816(d[f], ahi[ch], b[f][ch][1]);
            }
        }

        // ---- pool (in-reg rows + shfl over dx) + bias' + clamp + store ----
        const int ph = 2 * phb + t;
#pragma unroll
        for (int f = 0; f < 2; f++) {
            float c0 = fmaxf(d[f][0], d[f][2]);
            float c1 = fmaxf(d[f][1], d[f][3]);
            c0 = fmaxf(c0, __shfl_xor_sync(0xFFFFFFFFu, c0, 4));
            c1 = fmaxf(c1, __shfl_xor_sync(0xFFFFFFFFu, c1, 4));
            if (dx == f) {
                const int n0 = 8 * f + 2 * tig;
                const float y0 = fminf(fmaxf(c0 + __ldg(&g_cp.bias2[n0]),     0.0f), 1.0f);
                const float y1 = fminf(fmaxf(c1 + __ldg(&g_cp.bias2[n0 + 1]), 0.0f), 1.0f);
                float* o0 = out + (((size_t)(bi * OCN + n0)) * PHN + ph) * PWN + pwb + p;
                o0[0] = y0;
                o0[(size_t)PHN * PWN] = y1;
            }
        }
    }
}

extern "C" void kernel_launch(void* const* d_in, const int* in_sizes, int n_in,
                              void* d_out, int out_size) {
    const float* x     = (const float*)d_in[0];
    const float* w     = (const float*)d_in[1];
    const float* bias  = (const float*)d_in[2];
    const float* scale = (const float*)d_in[3];
    float* out = (float*)d_out;

    const int B = in_sizes[0] / (ICN * IH * IW);   // 32

    prep_kernel<<<1, 512>>>(w, bias, scale);

    dim3 block(128);                 // 4 warps x (4 pooled cols x 2 pooled rows)
    dim3 grid(PWN / 16, PHN / 2, B); // 16 x 128 x 32
    conv_mma_kernel<<<grid, block>>>(x, out);
}